// round 5
// baseline (speedup 1.0000x reference)
#include <cuda_runtime.h>

// FokkerPlanck2D step: f_new = max(0, f + dt*rhs), 9-point stencil with
// per-pixel weights from A (drift) and D (diffusion) at neighbor sites.
// Zero (vacuum) boundaries.
//
// Structure: i-pencil blocks, 128 threads x float4 = full 512-wide row,
// NBATCH=4 batches share coefficient rows, f rows rotate through 6-wide
// register windows; weights recomputed per iteration from L1-hot coeff rows.
// R5: halo values come from warp shuffles (neighbor lane registers) with
// 1-lane predicated loads at warp boundaries, instead of full-warp scalar
// LDGs (which cost as many L1 sectors as a vector load). ICH=16 -> grid 1024
// to remove the 3-vs-4 CTA/SM wave imbalance of grid 512.

static constexpr int NXC    = 512;
static constexpr int NYC    = 512;
static constexpr int ICH    = 16;         // i-rows per block
static constexpr int NBATCH = 4;          // batches per block
static constexpr int TPB    = NYC / 4;    // 128 threads

// Load a 6-wide window v[m] = row[j0 + m - 1] (zero outside [0,NYC)).
// Halos via intra-warp shuffle; warp-boundary lanes use a 1-lane scalar load.
__device__ __forceinline__ void win6_s(const float* __restrict__ row, int j0,
                                       int lane, bool Lg, bool Rg, float v[6]) {
    const float4 m4 = __ldg(reinterpret_cast<const float4*>(row + j0));
    float left  = __shfl_up_sync(0xffffffffu, m4.w, 1);
    float right = __shfl_down_sync(0xffffffffu, m4.x, 1);
    if (lane == 0)  left  = Lg ? __ldg(row + j0 - 1) : 0.0f;
    if (lane == 31) right = Rg ? __ldg(row + j0 + 4) : 0.0f;
    v[0] = left;
    v[1] = m4.x; v[2] = m4.y; v[3] = m4.z; v[4] = m4.w;
    v[5] = right;
}

__global__ __launch_bounds__(TPB, 4)
void fp2d_step_kernel(const float* __restrict__ f,
                      const float* __restrict__ A,
                      const float* __restrict__ D,
                      const float* __restrict__ dtp,
                      float* __restrict__ out) {
    const int tid  = threadIdx.x;
    const int lane = tid & 31;
    const int j0   = tid * 4;
    const bool L   = (tid > 0);
    const bool R   = (tid < TPB - 1);
    const int i0   = blockIdx.x * ICH;
    const long b0  = (long)blockIdx.y * NBATCH;

    const float dt  = __ldg(dtp);
    const float hdt = 0.5f  * dt;
    const float qdt = 0.25f * dt;

    const long plane = (long)NXC * NYC;
    const float* A0 = A;
    const float* A1 = A + plane;
    const float* D0 = D;
    const float* D1 = D + plane;
    const float* D2 = D + 2 * plane;

    // f windows: [m] = f[row][j0+m-1], rotated along i
    float fm[NBATCH][6], fc[NBATCH][6], fp[NBATCH][6];

    // ---------------- prologue: f rows i0-1 and i0 ----------------
    {
        const int r = i0 - 1;
        if (r >= 0) {
            const float* frow = f + (long)r * NYC;
            #pragma unroll
            for (int b = 0; b < NBATCH; ++b)
                win6_s(frow + (b0 + b) * plane, j0, lane, L, R, fm[b]);
        } else {
            #pragma unroll
            for (int b = 0; b < NBATCH; ++b)
                #pragma unroll
                for (int m = 0; m < 6; ++m) fm[b][m] = 0.0f;
        }
        const float* frow = f + (long)i0 * NYC;
        #pragma unroll
        for (int b = 0; b < NBATCH; ++b)
            win6_s(frow + (b0 + b) * plane, j0, lane, L, R, fc[b]);
    }

    // ---------------- main i-march ----------------
    for (int i = i0; i < i0 + ICH; ++i) {
        const int ip = i + 1;
        const int im = i - 1;
        const bool up_ok = (ip < NXC);
        const bool dn_ok = (im >= 0);

        // 1) load f row i+1 (the only DRAM-new data this iteration)
        if (up_ok) {
            const float* frow = f + (long)ip * NYC;
            #pragma unroll
            for (int b = 0; b < NBATCH; ++b)
                win6_s(frow + (b0 + b) * plane, j0, lane, L, R, fp[b]);
        } else {
            #pragma unroll
            for (int b = 0; b < NBATCH; ++b)
                #pragma unroll
                for (int m = 0; m < 6; ++m) fp[b][m] = 0.0f;
        }

        // 2) weights for output row i, recomputed from L1-hot coefficient rows
        float wxp[4], wxm[4], wdp[6], wdm[6], ccc[4], cyp[4], cym[4];
        if (up_ok) {
            const float4 a0 = __ldg(reinterpret_cast<const float4*>(A0 + (long)ip * NYC + j0));
            const float4 d0 = __ldg(reinterpret_cast<const float4*>(D0 + (long)ip * NYC + j0));
            wxp[0] = hdt * (d0.x - a0.x);
            wxp[1] = hdt * (d0.y - a0.y);
            wxp[2] = hdt * (d0.z - a0.z);
            wxp[3] = hdt * (d0.w - a0.w);
            float w[6];
            win6_s(D2 + (long)ip * NYC, j0, lane, L, R, w);
            #pragma unroll
            for (int m = 0; m < 6; ++m) wdp[m] = qdt * w[m];
        } else {
            #pragma unroll
            for (int k = 0; k < 4; ++k) wxp[k] = 0.f;
            #pragma unroll
            for (int m = 0; m < 6; ++m) wdp[m] = 0.f;
        }
        if (dn_ok) {
            const float4 a0 = __ldg(reinterpret_cast<const float4*>(A0 + (long)im * NYC + j0));
            const float4 d0 = __ldg(reinterpret_cast<const float4*>(D0 + (long)im * NYC + j0));
            wxm[0] = hdt * (d0.x + a0.x);
            wxm[1] = hdt * (d0.y + a0.y);
            wxm[2] = hdt * (d0.z + a0.z);
            wxm[3] = hdt * (d0.w + a0.w);
            float w[6];
            win6_s(D2 + (long)im * NYC, j0, lane, L, R, w);
            #pragma unroll
            for (int m = 0; m < 6; ++m) wdm[m] = qdt * w[m];
        } else {
            #pragma unroll
            for (int k = 0; k < 4; ++k) wxm[k] = 0.f;
            #pragma unroll
            for (int m = 0; m < 6; ++m) wdm[m] = 0.f;
        }
        {
            const float4 d0 = __ldg(reinterpret_cast<const float4*>(D0 + (long)i * NYC + j0));
            float d1w[6], a1w[6];
            win6_s(D1 + (long)i * NYC, j0, lane, L, R, d1w);
            win6_s(A1 + (long)i * NYC, j0, lane, L, R, a1w);
            const float d0v[4] = {d0.x, d0.y, d0.z, d0.w};
            #pragma unroll
            for (int k = 0; k < 4; ++k) {
                ccc[k] = 1.0f - dt * (d0v[k] + d1w[k + 1]);
                cyp[k] = hdt * (d1w[k + 2] - a1w[k + 2]);
                cym[k] = hdt * (d1w[k]     + a1w[k]);
            }
        }

        // 3) compute + streaming-store outputs for row i
        #pragma unroll
        for (int b = 0; b < NBATCH; ++b) {
            float rv[4];
            #pragma unroll
            for (int k = 0; k < 4; ++k) {
                const int j = k + 1;  // window index of column j0+k
                float v = ccc[k] * fc[b][j];
                v += wxp[k] * fp[b][j];
                v += wxm[k] * fm[b][j];
                v += cyp[k] * fc[b][j + 1];
                v += cym[k] * fc[b][j - 1];
                v += wdp[k + 2] * fp[b][k + 2];
                v -= wdp[k]     * fp[b][k];
                v -= wdm[k + 2] * fm[b][k + 2];
                v += wdm[k]     * fm[b][k];
                rv[k] = fmaxf(v, 0.0f);
            }
            float4 res;
            res.x = rv[0]; res.y = rv[1]; res.z = rv[2]; res.w = rv[3];
            __stcs(reinterpret_cast<float4*>(out + (b0 + b) * plane + (long)i * NYC + j0), res);
        }

        // 4) rotate f windows (fp -> fc -> fm)
        #pragma unroll
        for (int b = 0; b < NBATCH; ++b)
            #pragma unroll
            for (int m = 0; m < 6; ++m) {
                fm[b][m] = fc[b][m];
                fc[b][m] = fp[b][m];
            }
    }
}

extern "C" void kernel_launch(void* const* d_in, const int* in_sizes, int n_in,
                              void* d_out, int out_size) {
    const float* f  = (const float*)d_in[0];
    const float* A  = (const float*)d_in[1];
    const float* D  = (const float*)d_in[2];
    const float* dt = (const float*)d_in[3];
    float* out = (float*)d_out;

    const int plane = NXC * NYC;
    const int B = in_sizes[0] / plane;   // 128

    dim3 grid(NXC / ICH, B / NBATCH);    // (32, 32) = 1024 blocks
    fp2d_step_kernel<<<grid, TPB>>>(f, A, D, dt, out);
}

// round 6
// speedup vs baseline: 1.3885x; 1.3885x over previous
#include <cuda_runtime.h>

// FokkerPlanck2D step, two-kernel scheme:
//  K1 (tiny): fold A (drift) + D (diffusion) + dt into 9 per-point stencil
//             weight planes W[9][512][512] (batch-independent, boundary logic
//             baked in). ~15 MB of traffic, runs in a few us.
//  K2 (hot):  out(b,i,j) = max(0, sum_9 W_o(i,j) * f(b, i+di, j+dj)).
//             i-pencil blocks, 128 threads x float4 = full row, NBATCH=4
//             batches share the 9 weight vectors; f rows rotate through
//             6-wide register windows. No weight math, no coeff halos,
//             no boundary predicates in the hot loop.
// Weight planes: 0:Wc 1:Wxp 2:Wxm 3:Wyp 4:Wym 5:Wpp 6:Wpm 7:Wmp 8:Wmm
//   Wc  = 1 - dt*(D0+D1)(i,j)
//   Wxp = .5dt*(D0-A0)(i+1,j)   Wxm = .5dt*(D0+A0)(i-1,j)
//   Wyp = .5dt*(D1-A1)(i,j+1)   Wym = .5dt*(D1+A1)(i,j-1)
//   Wpp = +.25dt*D2(i+1,j+1)    Wpm = -.25dt*D2(i+1,j-1)
//   Wmp = -.25dt*D2(i-1,j+1)    Wmm = +.25dt*D2(i-1,j-1)
// (zero outside the grid = vacuum boundaries)

static constexpr int NXC    = 512;
static constexpr int NYC    = 512;
static constexpr int ICH    = 16;
static constexpr int NBATCH = 4;
static constexpr int TPB    = NYC / 4;      // 128
static constexpr long PLANE = (long)NXC * NYC;

__device__ float g_w[9 * NXC * NYC];        // 9.4 MB scratch (L2-resident)

__device__ __forceinline__ void win6_g(const float* __restrict__ row, int j0,
                                       bool Lg, bool Rg, float v[6]) {
    // v[m] = row[j0 + m - 1], zero-filled outside [0, NYC)
    const float4 m4 = __ldg(reinterpret_cast<const float4*>(row + j0));
    v[0] = Lg ? __ldg(row + j0 - 1) : 0.0f;
    v[1] = m4.x; v[2] = m4.y; v[3] = m4.z; v[4] = m4.w;
    v[5] = Rg ? __ldg(row + j0 + 4) : 0.0f;
}

__global__ __launch_bounds__(TPB)
void fp2d_weights_kernel(const float* __restrict__ A,
                         const float* __restrict__ D,
                         const float* __restrict__ dtp) {
    const int tid = threadIdx.x;
    const int j0  = tid * 4;
    const bool L  = (tid > 0);
    const bool R  = (tid < TPB - 1);
    const int i   = blockIdx.x;

    const float dt  = __ldg(dtp);
    const float hdt = 0.5f  * dt;
    const float qdt = 0.25f * dt;

    const float* A0 = A;
    const float* A1 = A + PLANE;
    const float* D0 = D;
    const float* D1 = D + PLANE;
    const float* D2 = D + 2 * PLANE;

    float w[9][4];

    // center-row weights
    {
        const float4 d0 = __ldg(reinterpret_cast<const float4*>(D0 + (long)i * NYC + j0));
        float d1w[6], a1w[6];
        win6_g(D1 + (long)i * NYC, j0, L, R, d1w);
        win6_g(A1 + (long)i * NYC, j0, L, R, a1w);
        const float d0v[4] = {d0.x, d0.y, d0.z, d0.w};
        #pragma unroll
        for (int k = 0; k < 4; ++k) {
            w[0][k] = 1.0f - dt * (d0v[k] + d1w[k + 1]);   // Wc
            w[3][k] = hdt * (d1w[k + 2] - a1w[k + 2]);     // Wyp
            w[4][k] = hdt * (d1w[k]     + a1w[k]);         // Wym
        }
    }
    // i+1 row weights
    {
        const int ip = i + 1;
        if (ip < NXC) {
            const float4 a0 = __ldg(reinterpret_cast<const float4*>(A0 + (long)ip * NYC + j0));
            const float4 d0 = __ldg(reinterpret_cast<const float4*>(D0 + (long)ip * NYC + j0));
            const float a0v[4] = {a0.x, a0.y, a0.z, a0.w};
            const float d0v[4] = {d0.x, d0.y, d0.z, d0.w};
            float d2w[6];
            win6_g(D2 + (long)ip * NYC, j0, L, R, d2w);
            #pragma unroll
            for (int k = 0; k < 4; ++k) {
                w[1][k] =  hdt * (d0v[k] - a0v[k]);        // Wxp
                w[5][k] =  qdt * d2w[k + 2];               // Wpp
                w[6][k] = -qdt * d2w[k];                   // Wpm
            }
        } else {
            #pragma unroll
            for (int k = 0; k < 4; ++k) { w[1][k] = 0.f; w[5][k] = 0.f; w[6][k] = 0.f; }
        }
    }
    // i-1 row weights
    {
        const int im = i - 1;
        if (im >= 0) {
            const float4 a0 = __ldg(reinterpret_cast<const float4*>(A0 + (long)im * NYC + j0));
            const float4 d0 = __ldg(reinterpret_cast<const float4*>(D0 + (long)im * NYC + j0));
            const float a0v[4] = {a0.x, a0.y, a0.z, a0.w};
            const float d0v[4] = {d0.x, d0.y, d0.z, d0.w};
            float d2w[6];
            win6_g(D2 + (long)im * NYC, j0, L, R, d2w);
            #pragma unroll
            for (int k = 0; k < 4; ++k) {
                w[2][k] =  hdt * (d0v[k] + a0v[k]);        // Wxm
                w[7][k] = -qdt * d2w[k + 2];               // Wmp
                w[8][k] =  qdt * d2w[k];                   // Wmm
            }
        } else {
            #pragma unroll
            for (int k = 0; k < 4; ++k) { w[2][k] = 0.f; w[7][k] = 0.f; w[8][k] = 0.f; }
        }
    }

    #pragma unroll
    for (int p = 0; p < 9; ++p) {
        float4 v;
        v.x = w[p][0]; v.y = w[p][1]; v.z = w[p][2]; v.w = w[p][3];
        *reinterpret_cast<float4*>(g_w + p * PLANE + (long)i * NYC + j0) = v;
    }
}

__global__ __launch_bounds__(TPB, 4)
void fp2d_step_kernel(const float* __restrict__ f,
                      float* __restrict__ out) {
    const int tid = threadIdx.x;
    const int j0  = tid * 4;
    const bool L  = (tid > 0);
    const bool R  = (tid < TPB - 1);
    const int i0  = blockIdx.x * ICH;
    const long b0 = (long)blockIdx.y * NBATCH;

    // f windows: [m] = f[row][j0+m-1], rotated along i
    float fm[NBATCH][6], fc[NBATCH][6], fp[NBATCH][6];

    // ---------------- prologue: f rows i0-1 and i0 ----------------
    {
        const int r = i0 - 1;
        if (r >= 0) {
            const float* frow = f + (long)r * NYC;
            #pragma unroll
            for (int b = 0; b < NBATCH; ++b)
                win6_g(frow + (b0 + b) * PLANE, j0, L, R, fm[b]);
        } else {
            #pragma unroll
            for (int b = 0; b < NBATCH; ++b)
                #pragma unroll
                for (int m = 0; m < 6; ++m) fm[b][m] = 0.0f;
        }
        const float* frow = f + (long)i0 * NYC;
        #pragma unroll
        for (int b = 0; b < NBATCH; ++b)
            win6_g(frow + (b0 + b) * PLANE, j0, L, R, fc[b]);
    }

    // ---------------- main i-march ----------------
    for (int i = i0; i < i0 + ICH; ++i) {
        const int ip = i + 1;

        // 1) load f row i+1 (the only DRAM-new data this iteration)
        if (ip < NXC) {
            const float* frow = f + (long)ip * NYC;
            #pragma unroll
            for (int b = 0; b < NBATCH; ++b)
                win6_g(frow + (b0 + b) * PLANE, j0, L, R, fp[b]);
        } else {
            #pragma unroll
            for (int b = 0; b < NBATCH; ++b)
                #pragma unroll
                for (int m = 0; m < 6; ++m) fp[b][m] = 0.0f;
        }

        // 2) load the 9 precomputed weight vectors for row i (L2-hot)
        float4 w[9];
        const float* wrow = g_w + (long)i * NYC + j0;
        #pragma unroll
        for (int p = 0; p < 9; ++p)
            w[p] = __ldg(reinterpret_cast<const float4*>(wrow + p * PLANE));

        // 3) compute + streaming-store outputs for row i
        #pragma unroll
        for (int b = 0; b < NBATCH; ++b) {
            float rv[4];
            #pragma unroll
            for (int k = 0; k < 4; ++k) {
                const float wc  = (&w[0].x)[k];
                const float wxp = (&w[1].x)[k];
                const float wxm = (&w[2].x)[k];
                const float wyp = (&w[3].x)[k];
                const float wym = (&w[4].x)[k];
                const float wpp = (&w[5].x)[k];
                const float wpm = (&w[6].x)[k];
                const float wmp = (&w[7].x)[k];
                const float wmm = (&w[8].x)[k];
                float v = wc  * fc[b][k + 1];
                v += wxp * fp[b][k + 1];
                v += wxm * fm[b][k + 1];
                v += wyp * fc[b][k + 2];
                v += wym * fc[b][k];
                v += wpp * fp[b][k + 2];
                v += wpm * fp[b][k];
                v += wmp * fm[b][k + 2];
                v += wmm * fm[b][k];
                rv[k] = fmaxf(v, 0.0f);
            }
            float4 res;
            res.x = rv[0]; res.y = rv[1]; res.z = rv[2]; res.w = rv[3];
            __stcs(reinterpret_cast<float4*>(out + (b0 + b) * PLANE + (long)i * NYC + j0), res);
        }

        // 4) rotate f windows (fp -> fc -> fm)
        #pragma unroll
        for (int b = 0; b < NBATCH; ++b)
            #pragma unroll
            for (int m = 0; m < 6; ++m) {
                fm[b][m] = fc[b][m];
                fc[b][m] = fp[b][m];
            }
    }
}

extern "C" void kernel_launch(void* const* d_in, const int* in_sizes, int n_in,
                              void* d_out, int out_size) {
    const float* f  = (const float*)d_in[0];
    const float* A  = (const float*)d_in[1];
    const float* D  = (const float*)d_in[2];
    const float* dt = (const float*)d_in[3];
    float* out = (float*)d_out;

    const int plane = NXC * NYC;
    const int B = in_sizes[0] / plane;   // 128

    fp2d_weights_kernel<<<NXC, TPB>>>(A, D, dt);
    dim3 grid(NXC / ICH, B / NBATCH);    // (32, 32)
    fp2d_step_kernel<<<grid, TPB>>>(f, out);
}